// round 7
// baseline (speedup 1.0000x reference)
#include <cuda_runtime.h>
#include <cstdint>
#include <cstddef>

#define MAXN 131072

// scratch (device globals: no allocation allowed)
__device__ float g_q[MAXN * 64];
__device__ float g_k[MAXN * 64];
__device__ float g_v[MAXN * 64];
__device__ float4 g_p4[MAXN];

// ---- packed fp32x2 ops (sm_103a FFMA2 path) ----
__device__ __forceinline__ float2 fma2(float2 a, float2 b, float2 c) {
    float2 d;
    asm("fma.rn.f32x2 %0, %1, %2, %3;"
        : "=l"(*(unsigned long long*)&d)
        : "l"(*(unsigned long long*)&a),
          "l"(*(unsigned long long*)&b),
          "l"(*(unsigned long long*)&c));
    return d;
}
__device__ __forceinline__ float2 add2(float2 a, float2 b) {
    float2 d;
    asm("add.rn.f32x2 %0, %1, %2;"
        : "=l"(*(unsigned long long*)&d)
        : "l"(*(unsigned long long*)&a),
          "l"(*(unsigned long long*)&b));
    return d;
}

// ============================================================================
// Kernel 1: fused q/k/v = x @ [Wq|Wk|Wv] + b, plus p -> g_p4 repack.
// ============================================================================
__global__ __launch_bounds__(256) void qkv_kernel(
    const float* __restrict__ x, const float* __restrict__ p,
    const float* __restrict__ Wq, const float* __restrict__ bq,
    const float* __restrict__ Wk, const float* __restrict__ bk,
    const float* __restrict__ Wv, const float* __restrict__ bv,
    int N)
{
    __shared__ float xs[64 * 65];          // 16.6 KB
    extern __shared__ float ws[];          // 64*192 floats = 48 KB
    const int tid = threadIdx.x;
    const int rowBase = blockIdx.x * 64;

    // fused weight: ws[k*192 + m*64 + c]
    {
        const float* Wm[3] = {Wq, Wk, Wv};
#pragma unroll
        for (int m = 0; m < 3; m++) {
            const float4* src = (const float4*)Wm[m];
            for (int e = tid; e < 1024; e += 256) {
                int k = e >> 4, c4 = e & 15;
                *(float4*)(ws + k * 192 + m * 64 + c4 * 4) = src[e];
            }
        }
    }
    // x tile (zero-pad past N), stride-65 rows
    for (int e = tid; e < 1024; e += 256) {
        int r = e >> 4, c4 = e & 15;
        float4 v = make_float4(0.f, 0.f, 0.f, 0.f);
        if (rowBase + r < N)
            v = *(const float4*)(x + (size_t)(rowBase + r) * 64 + c4 * 4);
        float* d = xs + r * 65 + c4 * 4;
        d[0] = v.x; d[1] = v.y; d[2] = v.z; d[3] = v.w;
    }
    // p repack (rows of this tile)
    if (tid < 64) {
        int row = rowBase + tid;
        if (row < N)
            g_p4[row] = make_float4(p[row * 3], p[row * 3 + 1], p[row * 3 + 2], 0.f);
    }
    __syncthreads();

    const int tx = tid & 15;      // 16 col groups (4 cols per matrix)
    const int ty = tid >> 4;      // 16 row groups (4 rows each)
    const int r0 = ty * 4;
    const int c0 = tx * 4;

    float2 acc[3][4][2];
    {
        const float* bias[3] = {bq, bk, bv};
#pragma unroll
        for (int m = 0; m < 3; m++) {
            float2 bA = *(const float2*)(bias[m] + c0);
            float2 bB = *(const float2*)(bias[m] + c0 + 2);
#pragma unroll
            for (int r = 0; r < 4; r++) { acc[m][r][0] = bA; acc[m][r][1] = bB; }
        }
    }

#pragma unroll 8
    for (int k = 0; k < 64; k++) {
        float xv[4];
#pragma unroll
        for (int r = 0; r < 4; r++) xv[r] = xs[(r0 + r) * 65 + k];
        const float* wk = ws + k * 192 + c0;
#pragma unroll
        for (int m = 0; m < 3; m++) {
            float4 w4 = *(const float4*)(wk + m * 64);
            float2 wA = make_float2(w4.x, w4.y);
            float2 wB = make_float2(w4.z, w4.w);
#pragma unroll
            for (int r = 0; r < 4; r++) {
                float2 xr = make_float2(xv[r], xv[r]);
                acc[m][r][0] = fma2(xr, wA, acc[m][r][0]);
                acc[m][r][1] = fma2(xr, wB, acc[m][r][1]);
            }
        }
    }

    float* outs[3] = {g_q, g_k, g_v};
#pragma unroll
    for (int m = 0; m < 3; m++) {
#pragma unroll
        for (int r = 0; r < 4; r++) {
            int row = rowBase + r0 + r;
            if (row < N)
                *(float4*)(outs[m] + (size_t)row * 64 + c0) =
                    make_float4(acc[m][r][0].x, acc[m][r][0].y,
                                acc[m][r][1].x, acc[m][r][1].y);
        }
    }
}

// ============================================================================
// Kernel 2: fused attention. 8 points per 128-thread block.
// (h0,h1,h2,nj) packed in one float4 living in the rv-row pad words
// (36jj+32..35) -> one broadcast LDS.128 per jj in stage & phase B, no
// shuffles. Softmax-weight overlay occupies words 12l..12l+7 (gaps == 8..11
// mod 12), provably disjoint from the h-pack. rv chunked by 32 channels.
// ============================================================================
struct __align__(16) K2C {
    float s1[64], bb1[64];
    float ws0[64], ws1[64], ws2[64], wsb[64];  // s1-scaled Wp2 rows + s1*bp2
    float r0[64], r1[64], r2[64], rb[64];      // raw Wp2 rows + bp2 (phase B)
    float wa[512];                             // Wa [64][8] (rows 32B-aligned)
    float wbm[64];                             // Wb [8][8]
    float s2[8], bb2[8], ba[8], bw[8];
    float wp1[9], bp1v[3], spv[3], bpv[3];
};

#define RV_J_STRIDE 36          // 32 ch + 4 pad (pad holds h-pack)
#define RV_PT_STRIDE 576        // 16 * 36
#define W_J_STRIDE 12           // softmax weight row (8 + 4 gap), 48B

__global__ __launch_bounds__(128, 8) void attn_kernel(
    const int* __restrict__ idx,
    const float* __restrict__ Wp1, const float* __restrict__ bp1,
    const float* __restrict__ gp,  const float* __restrict__ bp,
    const float* __restrict__ Wp2, const float* __restrict__ bp2,
    const float* __restrict__ g1,  const float* __restrict__ bb1,
    const float* __restrict__ Wa,  const float* __restrict__ ba,
    const float* __restrict__ g2,  const float* __restrict__ bb2,
    const float* __restrict__ Wb,  const float* __restrict__ bw,
    float* __restrict__ outp, int N)
{
    __shared__ K2C cst;
    extern __shared__ __align__(16) float rv_s[];  // 8 * RV_PT_STRIDE floats

    const int tid = threadIdx.x;
    const float RSQ = rsqrtf(1.f + 1e-5f);

    // ---- constant prep ----
    if (tid < 64) {
        float s1v = g1[tid] * RSQ;
        cst.s1[tid]  = s1v;
        cst.bb1[tid] = bb1[tid];
        float w0 = Wp2[tid], w1 = Wp2[64 + tid], w2 = Wp2[128 + tid], bb = bp2[tid];
        cst.r0[tid] = w0;        cst.r1[tid] = w1;
        cst.r2[tid] = w2;        cst.rb[tid] = bb;
        cst.ws0[tid] = w0 * s1v; cst.ws1[tid] = w1 * s1v;
        cst.ws2[tid] = w2 * s1v; cst.wsb[tid] = bb * s1v;
        cst.wbm[tid] = Wb[tid];
    }
    for (int e = tid; e < 512; e += 128) cst.wa[e] = Wa[e];
    if (tid < 8) {
        cst.s2[tid] = g2[tid] * RSQ;
        cst.bb2[tid] = bb2[tid];
        cst.ba[tid]  = ba[tid];
        cst.bw[tid]  = bw[tid];
    }
    if (tid >= 64 && tid < 73) cst.wp1[tid - 64] = Wp1[tid - 64];
    if (tid >= 80 && tid < 83) {
        int t = tid - 80;
        cst.bp1v[t] = bp1[t]; cst.spv[t] = gp[t] * RSQ; cst.bpv[t] = bp[t];
    }
    __syncthreads();

    const int pt = tid >> 4;          // 0..7
    const int l  = tid & 15;
    const int i0 = blockIdx.x * 8 + pt;
    const int i  = (i0 < N) ? i0 : 0;   // clamp; final store guarded

    float* rvp = rv_s + pt * RV_PT_STRIDE;

    // ---- prep (lane = neighbor l): nj + pe hidden -> packed float4 ----
    {
        const int nj = idx[i * 16 + l];
        float4 pc = g_p4[i];
        float4 pn = g_p4[nj];
        float prx = pn.x - pc.x, pry = pn.y - pc.y, prz = pn.z - pc.z;
        float u0 = cst.bp1v[0] + prx * cst.wp1[0] + pry * cst.wp1[3] + prz * cst.wp1[6];
        float u1 = cst.bp1v[1] + prx * cst.wp1[1] + pry * cst.wp1[4] + prz * cst.wp1[7];
        float u2 = cst.bp1v[2] + prx * cst.wp1[2] + pry * cst.wp1[5] + prz * cst.wp1[8];
        float h0 = fmaxf(fmaf(u0, cst.spv[0], cst.bpv[0]), 0.f);
        float h1 = fmaxf(fmaf(u1, cst.spv[1], cst.bpv[1]), 0.f);
        float h2 = fmaxf(fmaf(u2, cst.spv[2], cst.bpv[2]), 0.f);
        // h-pack lives in the rv row pad (words 36l+32..35)
        *(float4*)(rvp + l * RV_J_STRIDE + 32) =
            make_float4(h0, h1, h2, __int_as_float(nj));
    }
    __syncwarp();

    float2 a2[4];
#pragma unroll
    for (int q = 0; q < 4; q++) a2[q] = *(const float2*)(cst.ba + q * 2);

    // ---- chunked stage + phase A (2 chunks of 32 channels) ----
#pragma unroll
    for (int cb = 0; cb < 64; cb += 32) {
        // stage: lane owns channels (cb+2l, cb+2l+1)
        const int c0 = cb + l * 2;
        float2 s12 = *(const float2*)(cst.s1 + c0);
        float2 xq2;
        {
            float2 q2 = *(const float2*)(g_q + (size_t)i * 64 + c0);
            float2 b2v = *(const float2*)(cst.bb1 + c0);
            xq2.x = fmaf(-q2.x, s12.x, b2v.x);
            xq2.y = fmaf(-q2.y, s12.y, b2v.y);
        }
        float2 w02 = *(const float2*)(cst.ws0 + c0);
        float2 w12 = *(const float2*)(cst.ws1 + c0);
        float2 w22 = *(const float2*)(cst.ws2 + c0);
        float2 wb2 = *(const float2*)(cst.wsb + c0);

#pragma unroll 4
        for (int jj = 0; jj < 16; jj++) {
            float4 h4 = *(const float4*)(rvp + jj * RV_J_STRIDE + 32);  // bcast
            int   nb  = __float_as_int(h4.w);
            float2 kv = *(const float2*)(g_k + (size_t)nb * 64 + c0);
            float2 pe = fma2(make_float2(h4.x, h4.x), w02,
                        fma2(make_float2(h4.y, h4.y), w12,
                        fma2(make_float2(h4.z, h4.z), w22, wb2)));
            float2 arg = fma2(kv, s12, add2(xq2, pe));
            *(float2*)(rvp + jj * RV_J_STRIDE + l * 2) =
                make_float2(fmaxf(arg.x, 0.f), fmaxf(arg.y, 0.f));
        }
        __syncwarp();

        // phase A partial: lane = neighbor l; channels cb..cb+31
        {
            const float* rvj = rvp + l * RV_J_STRIDE;
#pragma unroll
            for (int c4 = 0; c4 < 8; c4++) {
                float4 rv4 = *(const float4*)(rvj + c4 * 4);
                float rvv[4] = {rv4.x, rv4.y, rv4.z, rv4.w};
#pragma unroll
                for (int ii = 0; ii < 4; ii++) {
                    const float* war = cst.wa + (cb + c4 * 4 + ii) * 8;
                    float4 wa0 = *(const float4*)(war);
                    float4 wa1 = *(const float4*)(war + 4);
                    float2 rr = make_float2(rvv[ii], rvv[ii]);
                    a2[0] = fma2(rr, make_float2(wa0.x, wa0.y), a2[0]);
                    a2[1] = fma2(rr, make_float2(wa0.z, wa0.w), a2[1]);
                    a2[2] = fma2(rr, make_float2(wa1.x, wa1.y), a2[2]);
                    a2[3] = fma2(rr, make_float2(wa1.z, wa1.w), a2[3]);
                }
            }
        }
        __syncwarp();
    }

    // ---- second MLP (8 -> 8) ----
    float2 b2[4];
#pragma unroll
    for (int q = 0; q < 4; q++) b2[q] = *(const float2*)(cst.bw + q * 2);
#pragma unroll
    for (int m = 0; m < 8; m++) {
        float avm = (m & 1) ? a2[m >> 1].y : a2[m >> 1].x;
        float t = fmaxf(fmaf(avm, cst.s2[m], cst.bb2[m]), 0.f);
        float2 tt = make_float2(t, t);
        const float2* wr = (const float2*)(cst.wbm + m * 8);
        b2[0] = fma2(tt, wr[0], b2[0]);
        b2[1] = fma2(tt, wr[1], b2[1]);
        b2[2] = fma2(tt, wr[2], b2[2]);
        b2[3] = fma2(tt, wr[3], b2[3]);
    }

    // ---- softmax over 16 neighbors, in place in b2 ----
    {
#pragma unroll
        for (int q = 0; q < 4; q++) {
            float2 v2 = b2[q];
            float mx0 = v2.x, mx1 = v2.y;
#pragma unroll
            for (int off = 8; off >= 1; off >>= 1) {
                mx0 = fmaxf(mx0, __shfl_xor_sync(0xffffffffu, mx0, off));
                mx1 = fmaxf(mx1, __shfl_xor_sync(0xffffffffu, mx1, off));
            }
            float e0 = __expf(v2.x - mx0);
            float e1 = __expf(v2.y - mx1);
            float s0 = e0, s1 = e1;
#pragma unroll
            for (int off = 8; off >= 1; off >>= 1) {
                s0 += __shfl_xor_sync(0xffffffffu, s0, off);
                s1 += __shfl_xor_sync(0xffffffffu, s1, off);
            }
            b2[q] = make_float2(__fdividef(e0, s0), __fdividef(e1, s1));
        }
    }
    // overlay softmax weights into dead rv words 12l..12l+7 (disjoint from h-pack)
    {
        float* wp = rvp + l * W_J_STRIDE;
        *(float4*)(wp)     = make_float4(b2[0].x, b2[0].y, b2[1].x, b2[1].y);
        *(float4*)(wp + 4) = make_float4(b2[2].x, b2[2].y, b2[3].x, b2[3].y);
    }
    __syncwarp();

    // ---- phase B: channel-parallel aggregation (coalesced v gather) ----
    const int c0 = l * 4;
    const int m0 = (l & 1) * 4;
    float4 rr0 = *(const float4*)(cst.r0 + c0);
    float4 rr1 = *(const float4*)(cst.r1 + c0);
    float4 rr2 = *(const float4*)(cst.r2 + c0);
    float4 rrb = *(const float4*)(cst.rb + c0);
    float2 acc01 = make_float2(0.f, 0.f), acc23 = make_float2(0.f, 0.f);
#pragma unroll 4
    for (int jj = 0; jj < 16; jj++) {
        float4 h4 = *(const float4*)(rvp + jj * RV_J_STRIDE + 32);  // bcast
        int   nb  = __float_as_int(h4.w);
        float4 wv = *(const float4*)(rvp + jj * W_J_STRIDE + m0);
        float4 v4 = *(const float4*)(g_v + (size_t)nb * 64 + c0);
        float2 pe01 = fma2(make_float2(h4.x, h4.x), make_float2(rr0.x, rr0.y),
                      fma2(make_float2(h4.y, h4.y), make_float2(rr1.x, rr1.y),
                      fma2(make_float2(h4.z, h4.z), make_float2(rr2.x, rr2.y),
                           make_float2(rrb.x, rrb.y))));
        float2 pe23 = fma2(make_float2(h4.x, h4.x), make_float2(rr0.z, rr0.w),
                      fma2(make_float2(h4.y, h4.y), make_float2(rr1.z, rr1.w),
                      fma2(make_float2(h4.z, h4.z), make_float2(rr2.z, rr2.w),
                           make_float2(rrb.z, rrb.w))));
        acc01 = fma2(add2(make_float2(v4.x, v4.y), pe01), make_float2(wv.x, wv.y), acc01);
        acc23 = fma2(add2(make_float2(v4.z, v4.w), pe23), make_float2(wv.z, wv.w), acc23);
    }
    if (i0 < N)
        *(float4*)(outp + (size_t)i0 * 64 + c0) =
            make_float4(acc01.x, acc01.y, acc23.x, acc23.y);
}

// ============================================================================
extern "C" void kernel_launch(void* const* d_in, const int* in_sizes, int n_in,
                              void* d_out, int out_size) {
    const float* p   = (const float*)d_in[0];
    const float* x   = (const float*)d_in[1];
    const int*   idx = (const int*)d_in[2];
    const float* Wq  = (const float*)d_in[3];  const float* bq  = (const float*)d_in[4];
    const float* Wk  = (const float*)d_in[5];  const float* bk  = (const float*)d_in[6];
    const float* Wv  = (const float*)d_in[7];  const float* bv  = (const float*)d_in[8];
    const float* Wp1 = (const float*)d_in[9];  const float* bp1 = (const float*)d_in[10];
    const float* gp  = (const float*)d_in[11]; const float* bp  = (const float*)d_in[12];
    const float* Wp2 = (const float*)d_in[13]; const float* bp2 = (const float*)d_in[14];
    const float* g1  = (const float*)d_in[15]; const float* bb1 = (const float*)d_in[16];
    const float* Wa  = (const float*)d_in[17]; const float* ba  = (const float*)d_in[18];
    const float* g2  = (const float*)d_in[19]; const float* bb2 = (const float*)d_in[20];
    const float* Wb  = (const float*)d_in[21]; const float* bw  = (const float*)d_in[22];

    int N = in_sizes[0] / 3;
    if (N > MAXN) N = MAXN;  // scratch bound (problem shape is N=100000)

    const int qkv_dyn  = 64 * 192 * (int)sizeof(float);           // 49152
    const int attn_dyn = 8 * RV_PT_STRIDE * (int)sizeof(float);   // 18432
    cudaFuncSetAttribute(qkv_kernel,  cudaFuncAttributeMaxDynamicSharedMemorySize, qkv_dyn);
    cudaFuncSetAttribute(attn_kernel, cudaFuncAttributeMaxDynamicSharedMemorySize, attn_dyn);

    qkv_kernel<<<(N + 63) / 64, 256, qkv_dyn>>>(x, p, Wq, bq, Wk, bk, Wv, bv, N);

    attn_kernel<<<(N + 7) / 8, 128, attn_dyn>>>(idx, Wp1, bp1, gp, bp, Wp2, bp2,
                                                g1, bb1, Wa, ba, g2, bb2, Wb, bw,
                                                (float*)d_out, N);
}

// round 8
// speedup vs baseline: 1.0977x; 1.0977x over previous
#include <cuda_runtime.h>
#include <cstdint>
#include <cstddef>

#define MAXN 131072

// scratch (device globals: no allocation allowed)
__device__ float g_q[MAXN * 64];
__device__ float g_k[MAXN * 64];
__device__ float g_v[MAXN * 64];
__device__ float4 g_p4[MAXN];

// ---- packed fp32x2 ops (sm_103a FFMA2 path) ----
__device__ __forceinline__ float2 fma2(float2 a, float2 b, float2 c) {
    float2 d;
    asm("fma.rn.f32x2 %0, %1, %2, %3;"
        : "=l"(*(unsigned long long*)&d)
        : "l"(*(unsigned long long*)&a),
          "l"(*(unsigned long long*)&b),
          "l"(*(unsigned long long*)&c));
    return d;
}
__device__ __forceinline__ float2 add2(float2 a, float2 b) {
    float2 d;
    asm("add.rn.f32x2 %0, %1, %2;"
        : "=l"(*(unsigned long long*)&d)
        : "l"(*(unsigned long long*)&a),
          "l"(*(unsigned long long*)&b));
    return d;
}

// ============================================================================
// Kernel 1: fused q/k/v = x @ [Wq|Wk|Wv] + b, plus p -> g_p4 repack.
// ============================================================================
__global__ __launch_bounds__(256) void qkv_kernel(
    const float* __restrict__ x, const float* __restrict__ p,
    const float* __restrict__ Wq, const float* __restrict__ bq,
    const float* __restrict__ Wk, const float* __restrict__ bk,
    const float* __restrict__ Wv, const float* __restrict__ bv,
    int N)
{
    __shared__ float xs[64 * 65];          // 16.6 KB
    extern __shared__ float ws[];          // 64*192 floats = 48 KB
    const int tid = threadIdx.x;
    const int rowBase = blockIdx.x * 64;

    // fused weight: ws[k*192 + m*64 + c]
    {
        const float* Wm[3] = {Wq, Wk, Wv};
#pragma unroll
        for (int m = 0; m < 3; m++) {
            const float4* src = (const float4*)Wm[m];
            for (int e = tid; e < 1024; e += 256) {
                int k = e >> 4, c4 = e & 15;
                *(float4*)(ws + k * 192 + m * 64 + c4 * 4) = src[e];
            }
        }
    }
    // x tile (zero-pad past N), stride-65 rows
    for (int e = tid; e < 1024; e += 256) {
        int r = e >> 4, c4 = e & 15;
        float4 v = make_float4(0.f, 0.f, 0.f, 0.f);
        if (rowBase + r < N)
            v = *(const float4*)(x + (size_t)(rowBase + r) * 64 + c4 * 4);
        float* d = xs + r * 65 + c4 * 4;
        d[0] = v.x; d[1] = v.y; d[2] = v.z; d[3] = v.w;
    }
    // p repack (rows of this tile)
    if (tid < 64) {
        int row = rowBase + tid;
        if (row < N)
            g_p4[row] = make_float4(p[row * 3], p[row * 3 + 1], p[row * 3 + 2], 0.f);
    }
    __syncthreads();

    const int tx = tid & 15;      // 16 col groups (4 cols per matrix)
    const int ty = tid >> 4;      // 16 row groups (4 rows each)
    const int r0 = ty * 4;
    const int c0 = tx * 4;

    float2 acc[3][4][2];
    {
        const float* bias[3] = {bq, bk, bv};
#pragma unroll
        for (int m = 0; m < 3; m++) {
            float2 bA = *(const float2*)(bias[m] + c0);
            float2 bB = *(const float2*)(bias[m] + c0 + 2);
#pragma unroll
            for (int r = 0; r < 4; r++) { acc[m][r][0] = bA; acc[m][r][1] = bB; }
        }
    }

#pragma unroll 8
    for (int k = 0; k < 64; k++) {
        float xv[4];
#pragma unroll
        for (int r = 0; r < 4; r++) xv[r] = xs[(r0 + r) * 65 + k];
        const float* wk = ws + k * 192 + c0;
#pragma unroll
        for (int m = 0; m < 3; m++) {
            float4 w4 = *(const float4*)(wk + m * 64);
            float2 wA = make_float2(w4.x, w4.y);
            float2 wB = make_float2(w4.z, w4.w);
#pragma unroll
            for (int r = 0; r < 4; r++) {
                float2 xr = make_float2(xv[r], xv[r]);
                acc[m][r][0] = fma2(xr, wA, acc[m][r][0]);
                acc[m][r][1] = fma2(xr, wB, acc[m][r][1]);
            }
        }
    }

    float* outs[3] = {g_q, g_k, g_v};
#pragma unroll
    for (int m = 0; m < 3; m++) {
#pragma unroll
        for (int r = 0; r < 4; r++) {
            int row = rowBase + r0 + r;
            if (row < N)
                *(float4*)(outs[m] + (size_t)row * 64 + c0) =
                    make_float4(acc[m][r][0].x, acc[m][r][0].y,
                                acc[m][r][1].x, acc[m][r][1].y);
        }
    }
}

// ============================================================================
// Kernel 2: fused attention. 8 points per 128-thread block.
// nj stays in lane-jj registers (shfl -> LDG address, no LDS->LDG chain);
// (h0,h1,h2) fetched via one broadcast LDS.128 from the rv-row pad
// (words 36jj+32..35). Per-point rv bases staggered by 8 banks so the two
// 16-lane halves' broadcasts hit disjoint bank groups. Softmax-weight
// overlay lives in dead rv words 12l..12l+7 (gaps == 8..11 mod 12).
// ============================================================================
struct __align__(16) K2C {
    float s1[64], bb1[64];
    float ws0[64], ws1[64], ws2[64], wsb[64];  // s1-scaled Wp2 rows + s1*bp2
    float r0[64], r1[64], r2[64], rb[64];      // raw Wp2 rows + bp2 (phase B)
    float wa[512];                             // Wa [64][8] (rows 32B-aligned)
    float wbm[64];                             // Wb [8][8]
    float s2[8], bb2[8], ba[8], bw[8];
    float wp1[9], bp1v[3], spv[3], bpv[3];
};

#define RV_J_STRIDE 36          // 32 ch + 4 pad (pad holds h-pack)
#define RV_PT_STRIDE 584        // 16*36 + 8 stagger; % 32 == 8
#define W_J_STRIDE 12           // softmax weight row (8 + 4 gap), 48B

__global__ __launch_bounds__(128, 8) void attn_kernel(
    const int* __restrict__ idx,
    const float* __restrict__ Wp1, const float* __restrict__ bp1,
    const float* __restrict__ gp,  const float* __restrict__ bp,
    const float* __restrict__ Wp2, const float* __restrict__ bp2,
    const float* __restrict__ g1,  const float* __restrict__ bb1,
    const float* __restrict__ Wa,  const float* __restrict__ ba,
    const float* __restrict__ g2,  const float* __restrict__ bb2,
    const float* __restrict__ Wb,  const float* __restrict__ bw,
    float* __restrict__ outp, int N)
{
    __shared__ K2C cst;
    extern __shared__ __align__(16) float rv_s[];  // 8 * RV_PT_STRIDE floats

    const int tid = threadIdx.x;
    const float RSQ = rsqrtf(1.f + 1e-5f);

    // ---- constant prep ----
    if (tid < 64) {
        float s1v = g1[tid] * RSQ;
        cst.s1[tid]  = s1v;
        cst.bb1[tid] = bb1[tid];
        float w0 = Wp2[tid], w1 = Wp2[64 + tid], w2 = Wp2[128 + tid], bb = bp2[tid];
        cst.r0[tid] = w0;        cst.r1[tid] = w1;
        cst.r2[tid] = w2;        cst.rb[tid] = bb;
        cst.ws0[tid] = w0 * s1v; cst.ws1[tid] = w1 * s1v;
        cst.ws2[tid] = w2 * s1v; cst.wsb[tid] = bb * s1v;
        cst.wbm[tid] = Wb[tid];
    }
    for (int e = tid; e < 512; e += 128) cst.wa[e] = Wa[e];
    if (tid < 8) {
        cst.s2[tid] = g2[tid] * RSQ;
        cst.bb2[tid] = bb2[tid];
        cst.ba[tid]  = ba[tid];
        cst.bw[tid]  = bw[tid];
    }
    if (tid >= 64 && tid < 73) cst.wp1[tid - 64] = Wp1[tid - 64];
    if (tid >= 80 && tid < 83) {
        int t = tid - 80;
        cst.bp1v[t] = bp1[t]; cst.spv[t] = gp[t] * RSQ; cst.bpv[t] = bp[t];
    }
    __syncthreads();

    const int pt = tid >> 4;          // 0..7
    const int l  = tid & 15;
    const int i0 = blockIdx.x * 8 + pt;
    const int i  = (i0 < N) ? i0 : 0;   // clamp; final store guarded

    float* rvp = rv_s + pt * RV_PT_STRIDE;

    // ---- prep (lane = neighbor l): nj in register + pe hidden -> pad ----
    const int nj = idx[i * 16 + l];
    {
        float4 pc = g_p4[i];
        float4 pn = g_p4[nj];
        float prx = pn.x - pc.x, pry = pn.y - pc.y, prz = pn.z - pc.z;
        float u0 = cst.bp1v[0] + prx * cst.wp1[0] + pry * cst.wp1[3] + prz * cst.wp1[6];
        float u1 = cst.bp1v[1] + prx * cst.wp1[1] + pry * cst.wp1[4] + prz * cst.wp1[7];
        float u2 = cst.bp1v[2] + prx * cst.wp1[2] + pry * cst.wp1[5] + prz * cst.wp1[8];
        float h0 = fmaxf(fmaf(u0, cst.spv[0], cst.bpv[0]), 0.f);
        float h1 = fmaxf(fmaf(u1, cst.spv[1], cst.bpv[1]), 0.f);
        float h2 = fmaxf(fmaf(u2, cst.spv[2], cst.bpv[2]), 0.f);
        *(float4*)(rvp + l * RV_J_STRIDE + 32) = make_float4(h0, h1, h2, 0.f);
    }
    __syncwarp();

    float2 a2[4];
#pragma unroll
    for (int q = 0; q < 4; q++) a2[q] = *(const float2*)(cst.ba + q * 2);

    // ---- chunked stage + phase A (2 chunks of 32 channels) ----
#pragma unroll
    for (int cb = 0; cb < 64; cb += 32) {
        // stage: lane owns channels (cb+2l, cb+2l+1)
        const int c0 = cb + l * 2;
        float2 s12 = *(const float2*)(cst.s1 + c0);
        float2 xq2;
        {
            float2 q2 = *(const float2*)(g_q + (size_t)i * 64 + c0);
            float2 b2v = *(const float2*)(cst.bb1 + c0);
            xq2.x = fmaf(-q2.x, s12.x, b2v.x);
            xq2.y = fmaf(-q2.y, s12.y, b2v.y);
        }
        float2 w02 = *(const float2*)(cst.ws0 + c0);
        float2 w12 = *(const float2*)(cst.ws1 + c0);
        float2 w22 = *(const float2*)(cst.ws2 + c0);
        float2 wb2 = *(const float2*)(cst.wsb + c0);

#pragma unroll 4
        for (int jj = 0; jj < 16; jj++) {
            int    nb = __shfl_sync(0xffffffffu, nj, jj, 16);        // reg -> LDG addr
            float2 kv = *(const float2*)(g_k + (size_t)nb * 64 + c0);
            float4 h4 = *(const float4*)(rvp + jj * RV_J_STRIDE + 32); // bcast LDS
            float2 pe = fma2(make_float2(h4.x, h4.x), w02,
                        fma2(make_float2(h4.y, h4.y), w12,
                        fma2(make_float2(h4.z, h4.z), w22, wb2)));
            float2 arg = fma2(kv, s12, add2(xq2, pe));
            *(float2*)(rvp + jj * RV_J_STRIDE + l * 2) =
                make_float2(fmaxf(arg.x, 0.f), fmaxf(arg.y, 0.f));
        }
        __syncwarp();

        // phase A partial: lane = neighbor l; channels cb..cb+31
        {
            const float* rvj = rvp + l * RV_J_STRIDE;
#pragma unroll
            for (int c4 = 0; c4 < 8; c4++) {
                float4 rv4 = *(const float4*)(rvj + c4 * 4);
                float rvv[4] = {rv4.x, rv4.y, rv4.z, rv4.w};
#pragma unroll
                for (int ii = 0; ii < 4; ii++) {
                    const float* war = cst.wa + (cb + c4 * 4 + ii) * 8;
                    float4 wa0 = *(const float4*)(war);
                    float4 wa1 = *(const float4*)(war + 4);
                    float2 rr = make_float2(rvv[ii], rvv[ii]);
                    a2[0] = fma2(rr, make_float2(wa0.x, wa0.y), a2[0]);
                    a2[1] = fma2(rr, make_float2(wa0.z, wa0.w), a2[1]);
                    a2[2] = fma2(rr, make_float2(wa1.x, wa1.y), a2[2]);
                    a2[3] = fma2(rr, make_float2(wa1.z, wa1.w), a2[3]);
                }
            }
        }
        __syncwarp();
    }

    // ---- second MLP (8 -> 8) ----
    float2 b2[4];
#pragma unroll
    for (int q = 0; q < 4; q++) b2[q] = *(const float2*)(cst.bw + q * 2);
#pragma unroll
    for (int m = 0; m < 8; m++) {
        float avm = (m & 1) ? a2[m >> 1].y : a2[m >> 1].x;
        float t = fmaxf(fmaf(avm, cst.s2[m], cst.bb2[m]), 0.f);
        float2 tt = make_float2(t, t);
        const float2* wr = (const float2*)(cst.wbm + m * 8);
        b2[0] = fma2(tt, wr[0], b2[0]);
        b2[1] = fma2(tt, wr[1], b2[1]);
        b2[2] = fma2(tt, wr[2], b2[2]);
        b2[3] = fma2(tt, wr[3], b2[3]);
    }

    // ---- softmax over 16 neighbors, in place in b2 ----
    {
#pragma unroll
        for (int q = 0; q < 4; q++) {
            float2 v2 = b2[q];
            float mx0 = v2.x, mx1 = v2.y;
#pragma unroll
            for (int off = 8; off >= 1; off >>= 1) {
                mx0 = fmaxf(mx0, __shfl_xor_sync(0xffffffffu, mx0, off));
                mx1 = fmaxf(mx1, __shfl_xor_sync(0xffffffffu, mx1, off));
            }
            float e0 = __expf(v2.x - mx0);
            float e1 = __expf(v2.y - mx1);
            float s0 = e0, s1 = e1;
#pragma unroll
            for (int off = 8; off >= 1; off >>= 1) {
                s0 += __shfl_xor_sync(0xffffffffu, s0, off);
                s1 += __shfl_xor_sync(0xffffffffu, s1, off);
            }
            b2[q] = make_float2(__fdividef(e0, s0), __fdividef(e1, s1));
        }
    }
    // overlay softmax weights into dead rv words 12l..12l+7 (disjoint from h-pack)
    {
        float* wp = rvp + l * W_J_STRIDE;
        *(float4*)(wp)     = make_float4(b2[0].x, b2[0].y, b2[1].x, b2[1].y);
        *(float4*)(wp + 4) = make_float4(b2[2].x, b2[2].y, b2[3].x, b2[3].y);
    }
    __syncwarp();

    // ---- phase B: channel-parallel aggregation (coalesced v gather) ----
    const int c0 = l * 4;
    const int m0 = (l & 1) * 4;
    float4 rr0 = *(const float4*)(cst.r0 + c0);
    float4 rr1 = *(const float4*)(cst.r1 + c0);
    float4 rr2 = *(const float4*)(cst.r2 + c0);
    float4 rrb = *(const float4*)(cst.rb + c0);
    float2 acc01 = make_float2(0.f, 0.f), acc23 = make_float2(0.f, 0.f);
#pragma unroll 4
    for (int jj = 0; jj < 16; jj++) {
        int    nb = __shfl_sync(0xffffffffu, nj, jj, 16);          // reg -> LDG addr
        float4 v4 = *(const float4*)(g_v + (size_t)nb * 64 + c0);
        float4 h4 = *(const float4*)(rvp + jj * RV_J_STRIDE + 32); // bcast LDS
        float4 wv = *(const float4*)(rvp + jj * W_J_STRIDE + m0);
        float2 pe01 = fma2(make_float2(h4.x, h4.x), make_float2(rr0.x, rr0.y),
                      fma2(make_float2(h4.y, h4.y), make_float2(rr1.x, rr1.y),
                      fma2(make_float2(h4.z, h4.z), make_float2(rr2.x, rr2.y),
                           make_float2(rrb.x, rrb.y))));
        float2 pe23 = fma2(make_float2(h4.x, h4.x), make_float2(rr0.z, rr0.w),
                      fma2(make_float2(h4.y, h4.y), make_float2(rr1.z, rr1.w),
                      fma2(make_float2(h4.z, h4.z), make_float2(rr2.z, rr2.w),
                           make_float2(rrb.z, rrb.w))));
        acc01 = fma2(add2(make_float2(v4.x, v4.y), pe01), make_float2(wv.x, wv.y), acc01);
        acc23 = fma2(add2(make_float2(v4.z, v4.w), pe23), make_float2(wv.z, wv.w), acc23);
    }
    if (i0 < N)
        *(float4*)(outp + (size_t)i0 * 64 + c0) =
            make_float4(acc01.x, acc01.y, acc23.x, acc23.y);
}

// ============================================================================
extern "C" void kernel_launch(void* const* d_in, const int* in_sizes, int n_in,
                              void* d_out, int out_size) {
    const float* p   = (const float*)d_in[0];
    const float* x   = (const float*)d_in[1];
    const int*   idx = (const int*)d_in[2];
    const float* Wq  = (const float*)d_in[3];  const float* bq  = (const float*)d_in[4];
    const float* Wk  = (const float*)d_in[5];  const float* bk  = (const float*)d_in[6];
    const float* Wv  = (const float*)d_in[7];  const float* bv  = (const float*)d_in[8];
    const float* Wp1 = (const float*)d_in[9];  const float* bp1 = (const float*)d_in[10];
    const float* gp  = (const float*)d_in[11]; const float* bp  = (const float*)d_in[12];
    const float* Wp2 = (const float*)d_in[13]; const float* bp2 = (const float*)d_in[14];
    const float* g1  = (const float*)d_in[15]; const float* bb1 = (const float*)d_in[16];
    const float* Wa  = (const float*)d_in[17]; const float* ba  = (const float*)d_in[18];
    const float* g2  = (const float*)d_in[19]; const float* bb2 = (const float*)d_in[20];
    const float* Wb  = (const float*)d_in[21]; const float* bw  = (const float*)d_in[22];

    int N = in_sizes[0] / 3;
    if (N > MAXN) N = MAXN;  // scratch bound (problem shape is N=100000)

    const int qkv_dyn  = 64 * 192 * (int)sizeof(float);           // 49152
    const int attn_dyn = 8 * RV_PT_STRIDE * (int)sizeof(float);   // 18688
    cudaFuncSetAttribute(qkv_kernel,  cudaFuncAttributeMaxDynamicSharedMemorySize, qkv_dyn);
    cudaFuncSetAttribute(attn_kernel, cudaFuncAttributeMaxDynamicSharedMemorySize, attn_dyn);

    qkv_kernel<<<(N + 63) / 64, 256, qkv_dyn>>>(x, p, Wq, bq, Wk, bk, Wv, bv, N);

    attn_kernel<<<(N + 7) / 8, 128, attn_dyn>>>(idx, Wp1, bp1, gp, bp, Wp2, bp2,
                                                g1, bb1, Wa, ba, g2, bb2, Wb, bw,
                                                (float*)d_out, N);
}